// round 1
// baseline (speedup 1.0000x reference)
#include <cuda_runtime.h>

#define FULL_MASK 0xffffffffu

static constexpr int Bb = 256;
static constexpr int Tt = 2048;
static constexpr int Dd = 64;

// ---- packed f32x2 helpers (Blackwell FFMA2 path, PTX-only) ----
__device__ __forceinline__ unsigned long long pack2(float lo, float hi) {
    unsigned long long r;
    asm("mov.b64 %0, {%1, %2};" : "=l"(r) : "f"(lo), "f"(hi));
    return r;
}
__device__ __forceinline__ float2 unpack2(unsigned long long v) {
    float2 f;
    asm("mov.b64 {%0, %1}, %2;" : "=f"(f.x), "=f"(f.y) : "l"(v));
    return f;
}
__device__ __forceinline__ unsigned long long ffma2(unsigned long long a,
                                                    unsigned long long b,
                                                    unsigned long long c) {
    unsigned long long r;
    asm("fma.rn.f32x2 %0, %1, %2, %3;" : "=l"(r) : "l"(a), "l"(b), "l"(c));
    return r;
}
__device__ __forceinline__ unsigned long long fadd2(unsigned long long a,
                                                    unsigned long long b) {
    unsigned long long r;
    asm("add.rn.f32x2 %0, %1, %2;" : "=l"(r) : "l"(a), "l"(b));
    return r;
}

// One warp per batch element. Lane l owns channels d0=2l, d1=2l+1.
__global__ __launch_bounds__(32) void crf_forward_kernel(
    const float* __restrict__ p,        // [B, T, D]
    const int*   __restrict__ y,        // [B, T, D] one-hot
    const int*   __restrict__ mask,     // [B, T] 1 = padding
    const float* __restrict__ tr,       // [D, D]
    float*       __restrict__ out)      // [B]
{
    const int b = blockIdx.x;
    const int l = threadIdx.x;
    const int d0 = 2 * l;
    const int d1 = 2 * l + 1;

    // Double-buffered duplicated-A: shA[q][e] = {A[e], A[e]} packed
    __shared__ unsigned long long shA[2][64];
    __shared__ int shLabel[2];

    // ---- preload exp(transition) columns d0,d1 as packed pairs into registers
    unsigned long long mtp[64];  // mtp[e] = {exp(tr[e][d0]), exp(tr[e][d1])}
    const float2* trp = reinterpret_cast<const float2*>(tr);
    #pragma unroll
    for (int e = 0; e < 64; ++e) {
        float2 v = trp[e * 32 + l];
        mtp[e] = pack2(__expf(v.x), __expf(v.y));
    }

    // ---- sequence length L = count of valid (mask==0) tokens
    int cnt = 0;
    const int* mb = mask + (size_t)b * Tt;
    #pragma unroll 4
    for (int t = l; t < Tt; t += 32) cnt += (mb[t] == 0);
    #pragma unroll
    for (int o = 16; o; o >>= 1) cnt += __shfl_xor_sync(FULL_MASK, cnt, o);
    const int L = cnt;  // guaranteed in [T/2, T]

    const float2* pb = reinterpret_cast<const float2*>(p) + (size_t)b * Tt * 32;
    const int2*   yb = reinterpret_cast<const int2*>(y)  + (size_t)b * Tt * 32;

    // ---- t = 0 init
    float2 pt0 = pb[l];
    float ax = pt0.x, ay = pt0.y;   // alpha[d0], alpha[d1]
    float s1 = 0.f, s2 = 0.f;       // emission / transition score partials

    int2 yv0 = yb[l];
    if (yv0.x) { s1 += pt0.x; shLabel[0] = d0; }
    if (yv0.y) { s1 += pt0.y; shLabel[0] = d1; }
    __syncwarp();

    // ---- forward recursion, exp-domain vec-mat per step
    for (int t = 1; t < L; ++t) {
        const int q = t & 1;

        float c = __shfl_sync(FULL_MASK, ax, 0);     // normalizer = alpha[0]
        float A0 = __expf(ax - c);
        float A1 = __expf(ay - c);
        reinterpret_cast<ulonglong2*>(shA[q])[l] =
            make_ulonglong2(pack2(A0, A0), pack2(A1, A1));

        float2 pt = pb[(size_t)t * 32 + l];
        int2   yv = yb[(size_t)t * 32 + l];

        // score bookkeeping (single owner lane per step; pre-sync, parity slots)
        if (yv.x | yv.y) {
            int   myd = yv.x ? d0 : d1;
            float pe  = yv.x ? pt.x : pt.y;
            int   prev = shLabel[q ^ 1];
            s1 += pe;
            s2 += __ldg(&tr[prev * 64 + myd]);
            shLabel[q] = myd;
        }
        __syncwarp();

        // s[d] = sum_e A[e] * exp(tr[e][d]) via packed FFMA2
        const ulonglong2* sa = reinterpret_cast<const ulonglong2*>(shA[q]);
        unsigned long long acc0 = 0ull, acc1 = 0ull, acc2 = 0ull, acc3 = 0ull;
        #pragma unroll
        for (int e2 = 0; e2 < 32; e2 += 2) {
            ulonglong2 v0 = sa[e2];
            ulonglong2 v1 = sa[e2 + 1];
            acc0 = ffma2(v0.x, mtp[2 * e2 + 0], acc0);
            acc1 = ffma2(v0.y, mtp[2 * e2 + 1], acc1);
            acc2 = ffma2(v1.x, mtp[2 * e2 + 2], acc2);
            acc3 = ffma2(v1.y, mtp[2 * e2 + 3], acc3);
        }
        unsigned long long accs = fadd2(fadd2(acc0, acc1), fadd2(acc2, acc3));
        float2 s = unpack2(accs);

        ax = pt.x + c + __logf(s.x);
        ay = pt.y + c + __logf(s.y);
    }

    // ---- logZ = logsumexp(alpha_{L-1})
    float m = fmaxf(ax, ay);
    #pragma unroll
    for (int o = 16; o; o >>= 1) m = fmaxf(m, __shfl_xor_sync(FULL_MASK, m, o));
    float se = __expf(ax - m) + __expf(ay - m);
    #pragma unroll
    for (int o = 16; o; o >>= 1) se += __shfl_xor_sync(FULL_MASK, se, o);
    #pragma unroll
    for (int o = 16; o; o >>= 1) s1 += __shfl_xor_sync(FULL_MASK, s1, o);
    #pragma unroll
    for (int o = 16; o; o >>= 1) s2 += __shfl_xor_sync(FULL_MASK, s2, o);

    if (l == 0) out[b] = m + __logf(se) - s1 - s2;
}

extern "C" void kernel_launch(void* const* d_in, const int* in_sizes, int n_in,
                              void* d_out, int out_size) {
    const float* p    = (const float*)d_in[0];
    const int*   y    = (const int*)d_in[1];
    const int*   mask = (const int*)d_in[2];
    const float* tr   = (const float*)d_in[3];
    float* out = (float*)d_out;

    crf_forward_kernel<<<Bb, 32>>>(p, y, mask, tr, out);
}

// round 2
// speedup vs baseline: 1.4534x; 1.4534x over previous
#include <cuda_runtime.h>

#define FULL_MASK 0xffffffffu

static constexpr int Bb = 256;
static constexpr int Tt = 2048;

// ---- packed f32x2 helpers (Blackwell FFMA2 path, PTX-only) ----
__device__ __forceinline__ unsigned long long pack2(float lo, float hi) {
    unsigned long long r;
    asm("mov.b64 %0, {%1, %2};" : "=l"(r) : "f"(lo), "f"(hi));
    return r;
}
__device__ __forceinline__ float2 unpack2(unsigned long long v) {
    float2 f;
    asm("mov.b64 {%0, %1}, %2;" : "=f"(f.x), "=f"(f.y) : "l"(v));
    return f;
}
__device__ __forceinline__ unsigned long long ffma2(unsigned long long a,
                                                    unsigned long long b,
                                                    unsigned long long c) {
    unsigned long long r;
    asm("fma.rn.f32x2 %0, %1, %2, %3;" : "=l"(r) : "l"(a), "l"(b), "l"(c));
    return r;
}
__device__ __forceinline__ unsigned long long fadd2(unsigned long long a,
                                                    unsigned long long b) {
    unsigned long long r;
    asm("add.rn.f32x2 %0, %1, %2;" : "=l"(r) : "l"(a), "l"(b));
    return r;
}

// 4 warps per block, one batch element per warp (each warp on its own SMSP).
// Lane l owns channels d0=2l, d1=2l+1.
__global__ __launch_bounds__(128, 1) void crf_forward_kernel(
    const float* __restrict__ p,        // [B, T, D]
    const int*   __restrict__ y,        // [B, T, D] one-hot
    const int*   __restrict__ mask,     // [B, T] 1 = padding
    const float* __restrict__ tr,       // [D, D]
    float*       __restrict__ out)      // [B]
{
    const int wid = threadIdx.x >> 5;
    const int l   = threadIdx.x & 31;
    const int b   = blockIdx.x * 4 + wid;

    __shared__ unsigned long long shA[4][2][64];  // per-warp double buffer

    // ---- sequence length L = count of valid (mask==0) tokens
    int cnt = 0;
    const int* mb = mask + (size_t)b * Tt;
    #pragma unroll 8
    for (int t = l; t < Tt; t += 32) cnt += (mb[t] == 0);
    #pragma unroll
    for (int o = 16; o; o >>= 1) cnt += __shfl_xor_sync(FULL_MASK, cnt, o);
    const int L = cnt;  // guaranteed >= T/2

    // ---- preload exp(transition) columns d0,d1 as packed pairs into registers
    unsigned long long mtp[64];  // mtp[e] = {exp(tr[e][d0]), exp(tr[e][d1])}
    const float2* trp = reinterpret_cast<const float2*>(tr);
    #pragma unroll
    for (int e = 0; e < 64; ++e) {
        float2 v = trp[e * 32 + l];
        mtp[e] = pack2(__expf(v.x), __expf(v.y));
    }

    const float2* pb = reinterpret_cast<const float2*>(p) + (size_t)b * Tt * 32 + l;
    const int2*   yb = reinterpret_cast<const int2*>(y)  + (size_t)b * Tt * 32 + l;

    // ---- t = 0 init
    float2 p0 = pb[0];
    int2   y0 = yb[0];
    float ax = p0.x, ay = p0.y;            // raw alpha[d0], alpha[d1]
    unsigned bal0 = __ballot_sync(FULL_MASK, (y0.x | y0.y) != 0);
    int src0 = __ffs(bal0) - 1;
    int vx0  = __shfl_sync(FULL_MASK, y0.x, src0);
    int prevLab = 2 * src0 + (vx0 ? 0 : 1);
    float s1 = 0.f, s2 = 0.f;
    if (l == src0) s1 = vx0 ? p0.x : p0.y;

    // stale-normalizer pipeline: step t uses alpha_{t-2}[0]
    float del1 = __shfl_sync(FULL_MASK, ax, 0);
    float del2 = del1;
    float pend1 = 0.f, pend2 = 0.f;        // pipelined transition gathers

    // ---- prefetch registers, distance 4
    float2 pf[4];
    int2   yf[4];
    #pragma unroll
    for (int i = 0; i < 4; ++i) {
        pf[i] = pb[(size_t)(1 + i) * 32];
        yf[i] = yb[(size_t)(1 + i) * 32];
    }

    unsigned long long* const bufA = shA[wid][0];
    unsigned long long* const bufB = shA[wid][1];

    // ---- forward recursion, exp-domain vec-mat per step
    for (int tb = 1; tb < Tt; tb += 4) {
        #pragma unroll
        for (int i = 0; i < 4; ++i) {
            const int t = tb + i;
            if (t >= L) break;             // warp-uniform

            float2 pt = pf[i];
            int2   yv = yf[i];
            int tn = t + 4; if (tn > Tt - 1) tn = Tt - 1;
            pf[i] = pb[(size_t)tn * 32];   // prefetch t+4 (clamped, harmless)
            yf[i] = yb[(size_t)tn * 32];

            // normalized exp of alpha_{t-1}, duplicated pairs, to shared
            float A0 = __expf(ax - del1);
            float A1 = __expf(ay - del1);
            unsigned long long* buf = (t & 1) ? bufB : bufA;
            reinterpret_cast<ulonglong2*>(buf)[l] =
                make_ulonglong2(pack2(A0, A0), pack2(A1, A1));
            __syncwarp();

            // s[d] = sum_e A[e] * exp(tr[e][d]) via packed FFMA2
            const ulonglong2* sa = reinterpret_cast<const ulonglong2*>(buf);
            unsigned long long acc0 = 0ull, acc1 = 0ull, acc2 = 0ull, acc3 = 0ull;
            #pragma unroll
            for (int e2 = 0; e2 < 32; e2 += 2) {
                ulonglong2 v0 = sa[e2];
                ulonglong2 v1 = sa[e2 + 1];
                acc0 = ffma2(v0.x, mtp[2 * e2 + 0], acc0);
                acc1 = ffma2(v0.y, mtp[2 * e2 + 1], acc1);
                acc2 = ffma2(v1.x, mtp[2 * e2 + 2], acc2);
                acc3 = ffma2(v1.y, mtp[2 * e2 + 3], acc3);
            }
            unsigned long long accs = fadd2(fadd2(acc0, acc1), fadd2(acc2, acc3));
            float2 s = unpack2(accs);
            float lx = __logf(s.x);
            float ly = __logf(s.y);

            // ---- scores, off the alpha critical path
            unsigned bal = __ballot_sync(FULL_MASK, (yv.x | yv.y) != 0);
            int srcl = __ffs(bal) - 1;
            int vx   = __shfl_sync(FULL_MASK, yv.x, srcl);
            int lab  = 2 * srcl + (vx ? 0 : 1);
            if (l == srcl) s1 += vx ? pt.x : pt.y;
            s2 += pend1;
            pend1 = pend2;
            pend2 = (l == 0) ? __ldg(&tr[prevLab * 64 + lab]) : 0.f;
            prevLab = lab;

            // alpha_t (raw)
            ax = pt.x + del1 + lx;
            ay = pt.y + del1 + ly;
            // rotate stale normalizer: issue shfl now, consume at t+2
            del1 = del2;
            del2 = __shfl_sync(FULL_MASK, ax, 0);
        }
        if (tb + 4 >= L) break;
    }
    s2 += pend1 + pend2;  // flush pipelined gathers

    // ---- logZ = logsumexp(alpha_{L-1}); reduce scores
    float m = fmaxf(ax, ay);
    #pragma unroll
    for (int o = 16; o; o >>= 1) m = fmaxf(m, __shfl_xor_sync(FULL_MASK, m, o));
    float se = __expf(ax - m) + __expf(ay - m);
    #pragma unroll
    for (int o = 16; o; o >>= 1) se += __shfl_xor_sync(FULL_MASK, se, o);
    #pragma unroll
    for (int o = 16; o; o >>= 1) s1 += __shfl_xor_sync(FULL_MASK, s1, o);
    #pragma unroll
    for (int o = 16; o; o >>= 1) s2 += __shfl_xor_sync(FULL_MASK, s2, o);

    if (l == 0) out[b] = m + __logf(se) - s1 - s2;
}

extern "C" void kernel_launch(void* const* d_in, const int* in_sizes, int n_in,
                              void* d_out, int out_size) {
    const float* p    = (const float*)d_in[0];
    const int*   y    = (const int*)d_in[1];
    const int*   mask = (const int*)d_in[2];
    const float* tr   = (const float*)d_in[3];
    float* out = (float*)d_out;

    crf_forward_kernel<<<Bb / 4, 128>>>(p, y, mask, tr, out);
}